// round 3
// baseline (speedup 1.0000x reference)
#include <cuda_runtime.h>

#define NN 50000
#define NE 800000
#define INF_ 128
#define C0 256      // HEADS*HID
#define HEADS 4
#define HID 64
#define OUTF 128

// ---------------- scratch (static device globals; allocation-free) ----------------
__device__ __align__(16) float g_feat0[(size_t)NN * C0];   // layer0 projected features
__device__ __align__(16) float g_h[(size_t)NN * C0];       // layer0 output == layer1 input
__device__ __align__(16) float g_feat1[(size_t)NN * OUTF]; // layer1 projected features
__device__ __align__(16) float g_e0[(size_t)NE * HEADS];   // per-edge logits (edge order)
__device__ __align__(16) float g_es[(size_t)NE * HEADS];   // per-edge logits/weights (CSR order); reused as float[NE] in layer1
__device__ int   g_srcs[NE];                               // src node per CSR slot
__device__ int   g_deg[NN];
__device__ int   g_off[NN + 1];
__device__ int   g_cur[NN];
__device__ __align__(16) float g_el0[NN * HEADS];
__device__ __align__(16) float g_er0[NN * HEADS];
__device__ float g_el1[NN];
__device__ float g_er1[NN];

__device__ __forceinline__ float lrelu(float v) { return v > 0.f ? v : 0.2f * v; }
__device__ __forceinline__ float elu1(float v) { return v > 0.f ? v : expm1f(v); }

// ---------------- init ----------------
__global__ void zero_deg_kernel() {
    int i = blockIdx.x * blockDim.x + threadIdx.x;
    if (i < NN) g_deg[i] = 0;
}

// ---------------- GEMM0: feat0 = x @ W0  (+ fused el0/er0) ----------------
// block: 256 threads, 8 rows; each thread owns one of 256 output cols for 8 rows.
__global__ void gemm0_kernel(const float* __restrict__ x, const float* __restrict__ W0,
                             const float* __restrict__ al0, const float* __restrict__ ar0) {
    __shared__ float xs[8][INF_];
    __shared__ float sEl[8][HEADS];
    __shared__ float sEr[8][HEADS];
    int tid = threadIdx.x;
    int row0 = blockIdx.x * 8;
    {   // cooperative load of 8x128 x-tile (1024 floats = 256 float4)
        int li = tid * 4;
        int r = li >> 7, c = li & 127;
        *(float4*)&xs[r][c] = *(const float4*)&x[(size_t)(row0 + r) * INF_ + c];
    }
    if (tid < 32) { ((float*)sEl)[tid] = 0.f; ((float*)sEr)[tid] = 0.f; }
    __syncthreads();

    int j = tid;
    float acc[8] = {0.f, 0.f, 0.f, 0.f, 0.f, 0.f, 0.f, 0.f};
#pragma unroll
    for (int k = 0; k < INF_; k += 4) {
        float w0 = W0[(k + 0) * C0 + j];
        float w1 = W0[(k + 1) * C0 + j];
        float w2 = W0[(k + 2) * C0 + j];
        float w3 = W0[(k + 3) * C0 + j];
#pragma unroll
        for (int r = 0; r < 8; r++) {
            float4 xv = *(float4*)&xs[r][k];
            acc[r] += xv.x * w0 + xv.y * w1 + xv.z * w2 + xv.w * w3;
        }
    }
    float a = al0[j], b = ar0[j];
    int h = j >> 6;
#pragma unroll
    for (int r = 0; r < 8; r++) {
        g_feat0[(size_t)(row0 + r) * C0 + j] = acc[r];
        float p = acc[r] * a, q = acc[r] * b;
#pragma unroll
        for (int o = 16; o > 0; o >>= 1) {
            p += __shfl_down_sync(0xffffffffu, p, o);
            q += __shfl_down_sync(0xffffffffu, q, o);
        }
        if ((tid & 31) == 0) { atomicAdd(&sEl[r][h], p); atomicAdd(&sEr[r][h], q); }
    }
    __syncthreads();
    if (tid < 32) {
        int r = tid >> 2, hh = tid & 3;
        g_el0[(row0 + r) * HEADS + hh] = sEl[r][hh];
        g_er0[(row0 + r) * HEADS + hh] = sEr[r][hh];
    }
}

// ---------------- per-edge logits + dst histogram ----------------
__global__ void edge0_kernel(const int* __restrict__ src, const int* __restrict__ dst) {
    int e = blockIdx.x * blockDim.x + threadIdx.x;
    if (e >= NE) return;
    int s = src[e], d = dst[e];
    atomicAdd(&g_deg[d], 1);
    float4 el = *(const float4*)&g_el0[s * HEADS];
    float4 er = *(const float4*)&g_er0[d * HEADS];
    float4 ev;
    ev.x = lrelu(el.x + er.x);
    ev.y = lrelu(el.y + er.y);
    ev.z = lrelu(el.z + er.z);
    ev.w = lrelu(el.w + er.w);
    *(float4*)&g_e0[(size_t)e * HEADS] = ev;
}

// ---------------- exclusive scan over degrees (single block) ----------------
__global__ void scan_kernel() {
    __shared__ int sh[1024];
    __shared__ int s_run;
    int tid = threadIdx.x;
    if (tid == 0) s_run = 0;
    const int CH = (NN + 1023) / 1024;
    for (int c = 0; c < CH; c++) {
        __syncthreads();
        int base = s_run;
        int idx = c * 1024 + tid;
        int v = (idx < NN) ? g_deg[idx] : 0;
        sh[tid] = v;
        __syncthreads();
        for (int o = 1; o < 1024; o <<= 1) {
            int t = (tid >= o) ? sh[tid - o] : 0;
            __syncthreads();
            sh[tid] += t;
            __syncthreads();
        }
        if (idx < NN) {
            int ex = base + sh[tid] - v;
            g_off[idx] = ex;
            g_cur[idx] = ex;
        }
        __syncthreads();
        if (tid == 0) s_run = base + sh[1023];
    }
    __syncthreads();
    if (tid == 0) g_off[NN] = s_run;
}

// ---------------- scatter edges into CSR slots ----------------
__global__ void scatter_kernel(const int* __restrict__ src, const int* __restrict__ dst) {
    int e = blockIdx.x * blockDim.x + threadIdx.x;
    if (e >= NE) return;
    int d = dst[e];
    int pos = atomicAdd(&g_cur[d], 1);
    g_srcs[pos] = src[e];
    *(float4*)&g_es[(size_t)pos * HEADS] = *(const float4*)&g_e0[(size_t)e * HEADS];
}

// ---------------- layer0 aggregation: warp per node ----------------
__global__ void agg0_kernel(const float* __restrict__ b0) {
    int warp = (blockIdx.x * blockDim.x + threadIdx.x) >> 5;
    int lane = threadIdx.x & 31;
    if (warp >= NN) return;
    int beg = g_off[warp], end = g_off[warp + 1];

    // 1) per-head max
    float4 mx = make_float4(-3.402823466e38f, -3.402823466e38f, -3.402823466e38f, -3.402823466e38f);
    for (int i = beg + lane; i < end; i += 32) {
        float4 e = *(const float4*)&g_es[(size_t)i * HEADS];
        mx.x = fmaxf(mx.x, e.x); mx.y = fmaxf(mx.y, e.y);
        mx.z = fmaxf(mx.z, e.z); mx.w = fmaxf(mx.w, e.w);
    }
#pragma unroll
    for (int o = 16; o > 0; o >>= 1) {
        mx.x = fmaxf(mx.x, __shfl_xor_sync(0xffffffffu, mx.x, o));
        mx.y = fmaxf(mx.y, __shfl_xor_sync(0xffffffffu, mx.y, o));
        mx.z = fmaxf(mx.z, __shfl_xor_sync(0xffffffffu, mx.z, o));
        mx.w = fmaxf(mx.w, __shfl_xor_sync(0xffffffffu, mx.w, o));
    }
    // 2) exp + per-head sum (store back ee)
    float4 sm = make_float4(0.f, 0.f, 0.f, 0.f);
    for (int i = beg + lane; i < end; i += 32) {
        float4 e = *(const float4*)&g_es[(size_t)i * HEADS];
        e.x = __expf(e.x - mx.x); e.y = __expf(e.y - mx.y);
        e.z = __expf(e.z - mx.z); e.w = __expf(e.w - mx.w);
        *(float4*)&g_es[(size_t)i * HEADS] = e;
        sm.x += e.x; sm.y += e.y; sm.z += e.z; sm.w += e.w;
    }
#pragma unroll
    for (int o = 16; o > 0; o >>= 1) {
        sm.x += __shfl_xor_sync(0xffffffffu, sm.x, o);
        sm.y += __shfl_xor_sync(0xffffffffu, sm.y, o);
        sm.z += __shfl_xor_sync(0xffffffffu, sm.z, o);
        sm.w += __shfl_xor_sync(0xffffffffu, sm.w, o);
    }
    __syncwarp();                           // make step-2 global writes visible warp-wide
    int h = lane >> 3;                      // this lane's 8 cols all belong to head h
    float den = (h == 0) ? sm.x : (h == 1) ? sm.y : (h == 2) ? sm.z : sm.w;
    float inv = (end > beg) ? (1.0f / den) : 0.f;

    // 3) weighted accumulate (register accumulators, whole warp covers 256 cols)
    float acc[8] = {0.f, 0.f, 0.f, 0.f, 0.f, 0.f, 0.f, 0.f};
    int j0 = lane * 8;
    for (int i = beg; i < end; i++) {
        float a = g_es[(size_t)i * HEADS + h] * inv;
        int s = g_srcs[i];
        const float4* fp = (const float4*)&g_feat0[(size_t)s * C0 + j0];
        float4 f0 = fp[0], f1 = fp[1];
        acc[0] += f0.x * a; acc[1] += f0.y * a; acc[2] += f0.z * a; acc[3] += f0.w * a;
        acc[4] += f1.x * a; acc[5] += f1.y * a; acc[6] += f1.z * a; acc[7] += f1.w * a;
    }
    // 4) bias + ELU -> g_h
    float4 o0, o1;
    o0.x = elu1(acc[0] + b0[j0 + 0]); o0.y = elu1(acc[1] + b0[j0 + 1]);
    o0.z = elu1(acc[2] + b0[j0 + 2]); o0.w = elu1(acc[3] + b0[j0 + 3]);
    o1.x = elu1(acc[4] + b0[j0 + 4]); o1.y = elu1(acc[5] + b0[j0 + 5]);
    o1.z = elu1(acc[6] + b0[j0 + 6]); o1.w = elu1(acc[7] + b0[j0 + 7]);
    float* hp = &g_h[(size_t)warp * C0 + j0];
    *(float4*)hp = o0;
    *(float4*)(hp + 4) = o1;
}

// ---------------- GEMM1: feat1 = h @ W1 (+ fused el1/er1) ----------------
__global__ void gemm1_kernel(const float* __restrict__ W1,
                             const float* __restrict__ al1, const float* __restrict__ ar1) {
    __shared__ float xs[8][C0];
    __shared__ float sEl[8];
    __shared__ float sEr[8];
    int tid = threadIdx.x;  // 128
    int row0 = blockIdx.x * 8;
#pragma unroll
    for (int t = 0; t < 4; t++) {
        int li = (tid + t * 128) * 4;
        int r = li >> 8, c = li & 255;
        *(float4*)&xs[r][c] = *(const float4*)&g_h[(size_t)(row0 + r) * C0 + c];
    }
    if (tid < 8) { sEl[tid] = 0.f; sEr[tid] = 0.f; }
    __syncthreads();

    int j = tid;
    float acc[8] = {0.f, 0.f, 0.f, 0.f, 0.f, 0.f, 0.f, 0.f};
#pragma unroll 4
    for (int k = 0; k < C0; k += 4) {
        float w0 = W1[(k + 0) * OUTF + j];
        float w1 = W1[(k + 1) * OUTF + j];
        float w2 = W1[(k + 2) * OUTF + j];
        float w3 = W1[(k + 3) * OUTF + j];
#pragma unroll
        for (int r = 0; r < 8; r++) {
            float4 xv = *(float4*)&xs[r][k];
            acc[r] += xv.x * w0 + xv.y * w1 + xv.z * w2 + xv.w * w3;
        }
    }
    float a = al1[j], b = ar1[j];
#pragma unroll
    for (int r = 0; r < 8; r++) {
        g_feat1[(size_t)(row0 + r) * OUTF + j] = acc[r];
        float p = acc[r] * a, q = acc[r] * b;
#pragma unroll
        for (int o = 16; o > 0; o >>= 1) {
            p += __shfl_down_sync(0xffffffffu, p, o);
            q += __shfl_down_sync(0xffffffffu, q, o);
        }
        if ((tid & 31) == 0) { atomicAdd(&sEl[r], p); atomicAdd(&sEr[r], q); }
    }
    __syncthreads();
    if (tid < 8) {
        g_el1[row0 + tid] = sEl[tid];
        g_er1[row0 + tid] = sEr[tid];
    }
}

// ---------------- layer1 aggregation: warp per node ----------------
__global__ void agg1_kernel(const float* __restrict__ b1, float* __restrict__ out) {
    int warp = (blockIdx.x * blockDim.x + threadIdx.x) >> 5;
    int lane = threadIdx.x & 31;
    if (warp >= NN) return;
    int beg = g_off[warp], end = g_off[warp + 1];
    float er = g_er1[warp];

    float mx = -3.402823466e38f;
    for (int i = beg + lane; i < end; i += 32) {
        float e = lrelu(g_el1[g_srcs[i]] + er);
        g_es[i] = e;
        mx = fmaxf(mx, e);
    }
#pragma unroll
    for (int o = 16; o > 0; o >>= 1) mx = fmaxf(mx, __shfl_xor_sync(0xffffffffu, mx, o));

    float sm = 0.f;
    for (int i = beg + lane; i < end; i += 32) {
        float ee = __expf(g_es[i] - mx);
        g_es[i] = ee;
        sm += ee;
    }
#pragma unroll
    for (int o = 16; o > 0; o >>= 1) sm += __shfl_xor_sync(0xffffffffu, sm, o);
    __syncwarp();                           // make weight writes visible warp-wide
    float inv = (end > beg) ? (1.0f / sm) : 0.f;

    float acc0 = 0.f, acc1 = 0.f, acc2 = 0.f, acc3 = 0.f;
    int j0 = lane * 4;
    for (int i = beg; i < end; i++) {
        float a = g_es[i] * inv;
        int s = g_srcs[i];
        float4 f = *(const float4*)&g_feat1[(size_t)s * OUTF + j0];
        acc0 += f.x * a; acc1 += f.y * a; acc2 += f.z * a; acc3 += f.w * a;
    }
    float4 o;
    o.x = elu1(acc0 + b1[j0 + 0]);
    o.y = elu1(acc1 + b1[j0 + 1]);
    o.z = elu1(acc2 + b1[j0 + 2]);
    o.w = elu1(acc3 + b1[j0 + 3]);
    *(float4*)&out[(size_t)warp * OUTF + j0] = o;
}

// ---------------- launch ----------------
extern "C" void kernel_launch(void* const* d_in, const int* in_sizes, int n_in,
                              void* d_out, int out_size) {
    const float* x   = (const float*)d_in[0];
    const int*   src = (const int*)d_in[1];
    const int*   dst = (const int*)d_in[2];
    const float* W0  = (const float*)d_in[3];
    const float* al0 = (const float*)d_in[4];
    const float* ar0 = (const float*)d_in[5];
    const float* b0  = (const float*)d_in[6];
    const float* W1  = (const float*)d_in[7];
    const float* al1 = (const float*)d_in[8];
    const float* ar1 = (const float*)d_in[9];
    const float* b1  = (const float*)d_in[10];
    float* out = (float*)d_out;

    zero_deg_kernel<<<(NN + 255) / 256, 256>>>();
    gemm0_kernel<<<NN / 8, 256>>>(x, W0, al0, ar0);
    edge0_kernel<<<(NE + 255) / 256, 256>>>(src, dst);
    scan_kernel<<<1, 1024>>>();
    scatter_kernel<<<(NE + 255) / 256, 256>>>(src, dst);
    agg0_kernel<<<NN / 8, 256>>>(b0);
    gemm1_kernel<<<NN / 8, 128>>>(W1, al1, ar1);
    agg1_kernel<<<NN / 8, 256>>>(b1, out);
}

// round 4
// speedup vs baseline: 1.1391x; 1.1391x over previous
#include <cuda_runtime.h>

#define NN 50000
#define NE 800000
#define INF_ 128
#define C0 256      // HEADS*HID
#define HEADS 4
#define HID 64
#define OUTF 128

#define SCAN_B 1024
#define SCAN_NB ((NN + SCAN_B - 1) / SCAN_B)   // 49

// ---------------- scratch (static device globals; allocation-free) ----------------
__device__ __align__(16) float g_feat0[(size_t)NN * C0];   // layer0 projected features
__device__ __align__(16) float g_h[(size_t)NN * C0];       // layer0 output == layer1 input
__device__ __align__(16) float g_feat1[(size_t)NN * OUTF]; // layer1 projected features
__device__ __align__(16) float g_e0[(size_t)NE * HEADS];   // per-edge logits (edge order)
__device__ __align__(16) float g_es[(size_t)NE * HEADS];   // per-edge logits/weights (CSR order); reused as float[NE] in layer1
__device__ int   g_srcs[NE];                               // src node per CSR slot
__device__ int   g_deg[NN];
__device__ int   g_off[NN + 1];
__device__ int   g_cur[NN];
__device__ int   g_bsum[SCAN_NB];                          // per-block degree sums
__device__ int   g_boff[SCAN_NB];                          // exclusive scan of block sums
__device__ __align__(16) float g_el0[NN * HEADS];
__device__ __align__(16) float g_er0[NN * HEADS];
__device__ float g_el1[NN];
__device__ float g_er1[NN];

__device__ __forceinline__ float lrelu(float v) { return v > 0.f ? v : 0.2f * v; }
__device__ __forceinline__ float elu1(float v) { return v > 0.f ? v : expm1f(v); }

// ---------------- init ----------------
__global__ void zero_deg_kernel() {
    int i = blockIdx.x * blockDim.x + threadIdx.x;
    if (i < NN) g_deg[i] = 0;
}

// ---------------- GEMM0: feat0 = x @ W0  (+ fused el0/er0) ----------------
__global__ void gemm0_kernel(const float* __restrict__ x, const float* __restrict__ W0,
                             const float* __restrict__ al0, const float* __restrict__ ar0) {
    __shared__ float xs[8][INF_];
    __shared__ float sEl[8][HEADS];
    __shared__ float sEr[8][HEADS];
    int tid = threadIdx.x;
    int row0 = blockIdx.x * 8;
    {   // cooperative load of 8x128 x-tile (1024 floats = 256 float4)
        int li = tid * 4;
        int r = li >> 7, c = li & 127;
        *(float4*)&xs[r][c] = *(const float4*)&x[(size_t)(row0 + r) * INF_ + c];
    }
    if (tid < 32) { ((float*)sEl)[tid] = 0.f; ((float*)sEr)[tid] = 0.f; }
    __syncthreads();

    int j = tid;
    float acc[8] = {0.f, 0.f, 0.f, 0.f, 0.f, 0.f, 0.f, 0.f};
#pragma unroll
    for (int k = 0; k < INF_; k += 4) {
        float w0 = W0[(k + 0) * C0 + j];
        float w1 = W0[(k + 1) * C0 + j];
        float w2 = W0[(k + 2) * C0 + j];
        float w3 = W0[(k + 3) * C0 + j];
#pragma unroll
        for (int r = 0; r < 8; r++) {
            float4 xv = *(float4*)&xs[r][k];
            acc[r] += xv.x * w0 + xv.y * w1 + xv.z * w2 + xv.w * w3;
        }
    }
    float a = al0[j], b = ar0[j];
    int h = j >> 6;
#pragma unroll
    for (int r = 0; r < 8; r++) {
        g_feat0[(size_t)(row0 + r) * C0 + j] = acc[r];
        float p = acc[r] * a, q = acc[r] * b;
#pragma unroll
        for (int o = 16; o > 0; o >>= 1) {
            p += __shfl_down_sync(0xffffffffu, p, o);
            q += __shfl_down_sync(0xffffffffu, q, o);
        }
        if ((tid & 31) == 0) { atomicAdd(&sEl[r][h], p); atomicAdd(&sEr[r][h], q); }
    }
    __syncthreads();
    if (tid < 32) {
        int r = tid >> 2, hh = tid & 3;
        g_el0[(row0 + r) * HEADS + hh] = sEl[r][hh];
        g_er0[(row0 + r) * HEADS + hh] = sEr[r][hh];
    }
}

// ---------------- per-edge logits + dst histogram ----------------
__global__ void edge0_kernel(const int* __restrict__ src, const int* __restrict__ dst) {
    int e = blockIdx.x * blockDim.x + threadIdx.x;
    if (e >= NE) return;
    int s = src[e], d = dst[e];
    atomicAdd(&g_deg[d], 1);
    float4 el = *(const float4*)&g_el0[s * HEADS];
    float4 er = *(const float4*)&g_er0[d * HEADS];
    float4 ev;
    ev.x = lrelu(el.x + er.x);
    ev.y = lrelu(el.y + er.y);
    ev.z = lrelu(el.z + er.z);
    ev.w = lrelu(el.w + er.w);
    *(float4*)&g_e0[(size_t)e * HEADS] = ev;
}

// ---------------- hierarchical scan: (1) per-block sums ----------------
__global__ void blocksum_kernel() {
    __shared__ int ws[32];
    int tid = threadIdx.x;
    int idx = blockIdx.x * SCAN_B + tid;
    int v = (idx < NN) ? g_deg[idx] : 0;
    int s = v;
#pragma unroll
    for (int o = 16; o > 0; o >>= 1) s += __shfl_down_sync(0xffffffffu, s, o);
    if ((tid & 31) == 0) ws[tid >> 5] = s;
    __syncthreads();
    if (tid < 32) {
        int t = ws[tid];
#pragma unroll
        for (int o = 16; o > 0; o >>= 1) t += __shfl_down_sync(0xffffffffu, t, o);
        if (tid == 0) g_bsum[blockIdx.x] = t;
    }
}

// ---------------- hierarchical scan: (2) scan the 49 block sums ----------------
__global__ void scan_sums_kernel() {
    __shared__ int w0sum;
    int tid = threadIdx.x;      // 64 threads
    int v = (tid < SCAN_NB) ? g_bsum[tid] : 0;
    int lane = tid & 31;
    int inc = v;
#pragma unroll
    for (int o = 1; o < 32; o <<= 1) {
        int t = __shfl_up_sync(0xffffffffu, inc, o);
        if (lane >= o) inc += t;
    }
    if (tid == 31) w0sum = inc;
    __syncthreads();
    int ex = inc - v + ((tid >= 32) ? w0sum : 0);
    if (tid < SCAN_NB) g_boff[tid] = ex;
}

// ---------------- hierarchical scan: (3) local scan + offset ----------------
__global__ void local_scan_kernel() {
    __shared__ int ws[32];
    int tid = threadIdx.x;
    int idx = blockIdx.x * SCAN_B + tid;
    int v = (idx < NN) ? g_deg[idx] : 0;
    int lane = tid & 31, wid = tid >> 5;
    int inc = v;
#pragma unroll
    for (int o = 1; o < 32; o <<= 1) {
        int t = __shfl_up_sync(0xffffffffu, inc, o);
        if (lane >= o) inc += t;
    }
    if (lane == 31) ws[wid] = inc;
    __syncthreads();
    if (tid < 32) {
        int t = ws[tid];
        int inc2 = t;
#pragma unroll
        for (int o = 1; o < 32; o <<= 1) {
            int u = __shfl_up_sync(0xffffffffu, inc2, o);
            if (tid >= o) inc2 += u;
        }
        ws[tid] = inc2 - t;   // exclusive warp offsets
    }
    __syncthreads();
    if (idx < NN) {
        int ex = g_boff[blockIdx.x] + ws[wid] + (inc - v);
        g_off[idx] = ex;
        g_cur[idx] = ex;
    }
    if (idx == 0) g_off[NN] = NE;   // Sum(deg) == NE by construction
}

// ---------------- scatter edges into CSR slots ----------------
__global__ void scatter_kernel(const int* __restrict__ src, const int* __restrict__ dst) {
    int e = blockIdx.x * blockDim.x + threadIdx.x;
    if (e >= NE) return;
    int d = dst[e];
    int pos = atomicAdd(&g_cur[d], 1);
    g_srcs[pos] = src[e];
    *(float4*)&g_es[(size_t)pos * HEADS] = *(const float4*)&g_e0[(size_t)e * HEADS];
}

// ---------------- layer0 aggregation: warp per node ----------------
__global__ void agg0_kernel(const float* __restrict__ b0) {
    int warp = (blockIdx.x * blockDim.x + threadIdx.x) >> 5;
    int lane = threadIdx.x & 31;
    if (warp >= NN) return;
    int beg = g_off[warp], end = g_off[warp + 1];

    // 1) per-head max
    float4 mx = make_float4(-3.402823466e38f, -3.402823466e38f, -3.402823466e38f, -3.402823466e38f);
    for (int i = beg + lane; i < end; i += 32) {
        float4 e = *(const float4*)&g_es[(size_t)i * HEADS];
        mx.x = fmaxf(mx.x, e.x); mx.y = fmaxf(mx.y, e.y);
        mx.z = fmaxf(mx.z, e.z); mx.w = fmaxf(mx.w, e.w);
    }
#pragma unroll
    for (int o = 16; o > 0; o >>= 1) {
        mx.x = fmaxf(mx.x, __shfl_xor_sync(0xffffffffu, mx.x, o));
        mx.y = fmaxf(mx.y, __shfl_xor_sync(0xffffffffu, mx.y, o));
        mx.z = fmaxf(mx.z, __shfl_xor_sync(0xffffffffu, mx.z, o));
        mx.w = fmaxf(mx.w, __shfl_xor_sync(0xffffffffu, mx.w, o));
    }
    // 2) exp + per-head sum (store back ee)
    float4 sm = make_float4(0.f, 0.f, 0.f, 0.f);
    for (int i = beg + lane; i < end; i += 32) {
        float4 e = *(const float4*)&g_es[(size_t)i * HEADS];
        e.x = __expf(e.x - mx.x); e.y = __expf(e.y - mx.y);
        e.z = __expf(e.z - mx.z); e.w = __expf(e.w - mx.w);
        *(float4*)&g_es[(size_t)i * HEADS] = e;
        sm.x += e.x; sm.y += e.y; sm.z += e.z; sm.w += e.w;
    }
#pragma unroll
    for (int o = 16; o > 0; o >>= 1) {
        sm.x += __shfl_xor_sync(0xffffffffu, sm.x, o);
        sm.y += __shfl_xor_sync(0xffffffffu, sm.y, o);
        sm.z += __shfl_xor_sync(0xffffffffu, sm.z, o);
        sm.w += __shfl_xor_sync(0xffffffffu, sm.w, o);
    }
    __syncwarp();                           // make step-2 global writes visible warp-wide
    int h = lane >> 3;                      // this lane's 8 cols all belong to head h
    float den = (h == 0) ? sm.x : (h == 1) ? sm.y : (h == 2) ? sm.z : sm.w;
    float inv = (end > beg) ? (1.0f / den) : 0.f;

    // 3) weighted accumulate (register accumulators, whole warp covers 256 cols)
    float acc[8] = {0.f, 0.f, 0.f, 0.f, 0.f, 0.f, 0.f, 0.f};
    int j0 = lane * 8;
    for (int i = beg; i < end; i++) {
        float a = g_es[(size_t)i * HEADS + h] * inv;
        int s = g_srcs[i];
        const float4* fp = (const float4*)&g_feat0[(size_t)s * C0 + j0];
        float4 f0 = fp[0], f1 = fp[1];
        acc[0] += f0.x * a; acc[1] += f0.y * a; acc[2] += f0.z * a; acc[3] += f0.w * a;
        acc[4] += f1.x * a; acc[5] += f1.y * a; acc[6] += f1.z * a; acc[7] += f1.w * a;
    }
    // 4) bias + ELU -> g_h
    float4 o0, o1;
    o0.x = elu1(acc[0] + b0[j0 + 0]); o0.y = elu1(acc[1] + b0[j0 + 1]);
    o0.z = elu1(acc[2] + b0[j0 + 2]); o0.w = elu1(acc[3] + b0[j0 + 3]);
    o1.x = elu1(acc[4] + b0[j0 + 4]); o1.y = elu1(acc[5] + b0[j0 + 5]);
    o1.z = elu1(acc[6] + b0[j0 + 6]); o1.w = elu1(acc[7] + b0[j0 + 7]);
    float* hp = &g_h[(size_t)warp * C0 + j0];
    *(float4*)hp = o0;
    *(float4*)(hp + 4) = o1;
}

// ---------------- GEMM1: feat1 = h @ W1 (+ fused el1/er1) ----------------
__global__ void gemm1_kernel(const float* __restrict__ W1,
                             const float* __restrict__ al1, const float* __restrict__ ar1) {
    __shared__ float xs[8][C0];
    __shared__ float sEl[8];
    __shared__ float sEr[8];
    int tid = threadIdx.x;  // 128
    int row0 = blockIdx.x * 8;
#pragma unroll
    for (int t = 0; t < 4; t++) {
        int li = (tid + t * 128) * 4;
        int r = li >> 8, c = li & 255;
        *(float4*)&xs[r][c] = *(const float4*)&g_h[(size_t)(row0 + r) * C0 + c];
    }
    if (tid < 8) { sEl[tid] = 0.f; sEr[tid] = 0.f; }
    __syncthreads();

    int j = tid;
    float acc[8] = {0.f, 0.f, 0.f, 0.f, 0.f, 0.f, 0.f, 0.f};
#pragma unroll 4
    for (int k = 0; k < C0; k += 4) {
        float w0 = W1[(k + 0) * OUTF + j];
        float w1 = W1[(k + 1) * OUTF + j];
        float w2 = W1[(k + 2) * OUTF + j];
        float w3 = W1[(k + 3) * OUTF + j];
#pragma unroll
        for (int r = 0; r < 8; r++) {
            float4 xv = *(float4*)&xs[r][k];
            acc[r] += xv.x * w0 + xv.y * w1 + xv.z * w2 + xv.w * w3;
        }
    }
    float a = al1[j], b = ar1[j];
#pragma unroll
    for (int r = 0; r < 8; r++) {
        g_feat1[(size_t)(row0 + r) * OUTF + j] = acc[r];
        float p = acc[r] * a, q = acc[r] * b;
#pragma unroll
        for (int o = 16; o > 0; o >>= 1) {
            p += __shfl_down_sync(0xffffffffu, p, o);
            q += __shfl_down_sync(0xffffffffu, q, o);
        }
        if ((tid & 31) == 0) { atomicAdd(&sEl[r], p); atomicAdd(&sEr[r], q); }
    }
    __syncthreads();
    if (tid < 8) {
        g_el1[row0 + tid] = sEl[tid];
        g_er1[row0 + tid] = sEr[tid];
    }
}

// ---------------- layer1 aggregation: warp per node ----------------
__global__ void agg1_kernel(const float* __restrict__ b1, float* __restrict__ out) {
    int warp = (blockIdx.x * blockDim.x + threadIdx.x) >> 5;
    int lane = threadIdx.x & 31;
    if (warp >= NN) return;
    int beg = g_off[warp], end = g_off[warp + 1];
    float er = g_er1[warp];

    float mx = -3.402823466e38f;
    for (int i = beg + lane; i < end; i += 32) {
        float e = lrelu(g_el1[g_srcs[i]] + er);
        g_es[i] = e;
        mx = fmaxf(mx, e);
    }
#pragma unroll
    for (int o = 16; o > 0; o >>= 1) mx = fmaxf(mx, __shfl_xor_sync(0xffffffffu, mx, o));

    float sm = 0.f;
    for (int i = beg + lane; i < end; i += 32) {
        float ee = __expf(g_es[i] - mx);
        g_es[i] = ee;
        sm += ee;
    }
#pragma unroll
    for (int o = 16; o > 0; o >>= 1) sm += __shfl_xor_sync(0xffffffffu, sm, o);
    __syncwarp();                           // make weight writes visible warp-wide
    float inv = (end > beg) ? (1.0f / sm) : 0.f;

    float acc0 = 0.f, acc1 = 0.f, acc2 = 0.f, acc3 = 0.f;
    int j0 = lane * 4;
    for (int i = beg; i < end; i++) {
        float a = g_es[i] * inv;
        int s = g_srcs[i];
        float4 f = *(const float4*)&g_feat1[(size_t)s * OUTF + j0];
        acc0 += f.x * a; acc1 += f.y * a; acc2 += f.z * a; acc3 += f.w * a;
    }
    float4 o;
    o.x = elu1(acc0 + b1[j0 + 0]);
    o.y = elu1(acc1 + b1[j0 + 1]);
    o.z = elu1(acc2 + b1[j0 + 2]);
    o.w = elu1(acc3 + b1[j0 + 3]);
    *(float4*)&out[(size_t)warp * OUTF + j0] = o;
}

// ---------------- launch ----------------
extern "C" void kernel_launch(void* const* d_in, const int* in_sizes, int n_in,
                              void* d_out, int out_size) {
    const float* x   = (const float*)d_in[0];
    const int*   src = (const int*)d_in[1];
    const int*   dst = (const int*)d_in[2];
    const float* W0  = (const float*)d_in[3];
    const float* al0 = (const float*)d_in[4];
    const float* ar0 = (const float*)d_in[5];
    const float* b0  = (const float*)d_in[6];
    const float* W1  = (const float*)d_in[7];
    const float* al1 = (const float*)d_in[8];
    const float* ar1 = (const float*)d_in[9];
    const float* b1  = (const float*)d_in[10];
    float* out = (float*)d_out;

    zero_deg_kernel<<<(NN + 255) / 256, 256>>>();
    gemm0_kernel<<<NN / 8, 256>>>(x, W0, al0, ar0);
    edge0_kernel<<<(NE + 255) / 256, 256>>>(src, dst);
    blocksum_kernel<<<SCAN_NB, SCAN_B>>>();
    scan_sums_kernel<<<1, 64>>>();
    local_scan_kernel<<<SCAN_NB, SCAN_B>>>();
    scatter_kernel<<<(NE + 255) / 256, 256>>>(src, dst);
    agg0_kernel<<<NN / 8, 256>>>(b0);
    gemm1_kernel<<<NN / 8, 128>>>(W1, al1, ar1);
    agg1_kernel<<<NN / 8, 256>>>(b1, out);
}